// round 15
// baseline (speedup 1.0000x reference)
#include <cuda_runtime.h>
#include <cstdint>

#define SEQ 20
#define DK  64
#define THREADS 128
#define GRID 740              // persistent: 5 blocks/SM * 148 SMs

#define SSW 20                // sS row stride (floats)
#define WTS 22                // sW2 row stride (ull pairs)

// per-buffer float offsets (Q,K,V rows are 64 floats, XOR-swizzled slots)
#define OQ 0
#define OK 1280
#define OV 2560
#define OM 3840               // mask: 400 floats [q*20+k]
#define BUFB 4240             // floats per buffer

typedef unsigned long long ull;

__device__ __forceinline__ ull fma2(ull a, ull b, ull c) {
    ull d;
    asm("fma.rn.f32x2 %0, %1, %2, %3;" : "=l"(d) : "l"(a), "l"(b), "l"(c));
    return d;
}
__device__ __forceinline__ ull pack2(float lo, float hi) {
    ull r;
    asm("mov.b64 %0, {%1, %2};" : "=l"(r) : "f"(lo), "f"(hi));
    return r;
}
__device__ __forceinline__ float2 unpack2(ull v) {
    float2 r;
    asm("mov.b64 {%0, %1}, %2;" : "=f"(r.x), "=f"(r.y) : "l"(v));
    return r;
}
__device__ __forceinline__ float lohi(ull v) {
    float2 r = unpack2(v);
    return r.x + r.y;
}

__device__ __forceinline__ void cp16(unsigned int saddr, const void* g) {
    asm volatile("cp.async.cg.shared.global [%0], [%1], 16;" :: "r"(saddr), "l"(g));
}

// XOR swizzle: float4-slot c4 of row stored at slot (c4 ^ (row>>2)) & 15
__device__ __forceinline__ void issue_loads(const float4* __restrict__ Q4,
                                            const float4* __restrict__ K4,
                                            const float4* __restrict__ V4,
                                            const float4* __restrict__ M4,
                                            long bh, float* buf, int tid)
{
    unsigned int sb = (unsigned int)__cvta_generic_to_shared(buf);
    const float4* q = Q4 + bh * 320;
    const float4* k = K4 + bh * 320;
    const float4* v = V4 + bh * 320;
    #pragma unroll
    for (int r = 0; r < 3; r++) {
        int i = tid + r * THREADS;
        if (i < 320) {
            int row = i >> 4, c4 = i & 15;
            unsigned int off = (unsigned int)(row * DK + 4 * ((c4 ^ (row >> 2)) & 15)) * 4u;
            cp16(sb + (OQ * 4u) + off, q + i);
            cp16(sb + (OK * 4u) + off, k + i);
            cp16(sb + (OV * 4u) + off, v + i);
        }
    }
    if (tid < 100)
        cp16(sb + (OM + 4 * tid) * 4u, M4 + bh * 100 + tid);
}

__global__ __launch_bounds__(THREADS, 5)
void sdpa_rel_kernel(const float* __restrict__ Qg,
                     const float* __restrict__ Kg,
                     const float* __restrict__ Vg,
                     const float* __restrict__ Mg,
                     float* __restrict__ deAtt,
                     float* __restrict__ attnOut,
                     int total)
{
    __shared__ __align__(16) float sBuf[2 * BUFB];
    __shared__ __align__(16) float sS[SEQ * SSW];    // raw scores, row-major
    __shared__ __align__(16) ull   sW2[SEQ * WTS];   // W^T as (w,w) pairs: [k*WTS+q]

    const int tid  = threadIdx.x;
    const int wid  = tid >> 5;
    const int lane = tid & 31;
    const int G    = gridDim.x;

    const float4* Q4 = (const float4*)Qg;
    const float4* K4 = (const float4*)Kg;
    const float4* V4 = (const float4*)Vg;
    const float4* M4 = (const float4*)Mg;

    issue_loads(Q4, K4, V4, M4, blockIdx.x, sBuf, tid);
    asm volatile("cp.async.commit_group;" ::: "memory");

    int it = 0;
    for (long bh = blockIdx.x; bh < total; bh += G, it++) {
        float* buf = sBuf + (it & 1) * BUFB;

        if (bh + G < total) {
            issue_loads(Q4, K4, V4, M4, bh + G, sBuf + ((it + 1) & 1) * BUFB, tid);
            asm volatile("cp.async.commit_group;" ::: "memory");
            asm volatile("cp.async.wait_group 1;" ::: "memory");
        } else {
            asm volatile("cp.async.wait_group 0;" ::: "memory");
        }
        __syncthreads();

        const int special = (3 - it) & 3;        // warp doing A-half0 + row this iter
        const int helper  = special ^ 1;         // warp doing A-half1 (other SMSP)

        // ---- Phase A: S = Q K^T, 4q x 4k tiles, 25 lanes on TWO warps (k-halves) ----
        if ((wid == special || wid == helper) && lane < 25) {
            const int kh = (wid == helper);      // 0 or 1: which pair of k-columns
            const int q0 = (lane / 5) * 4;
            const int k0 = (lane % 5) * 4;
            const int jq = q0 >> 2;
            const int jk = k0 >> 2;
            const float* Qb = buf + OQ + q0 * DK;
            const float* Kb = buf + OK + (k0 + 2 * kh) * DK;
            ull acc[4][2] = {};
            #pragma unroll
            for (int d4 = 0; d4 < DK / 4; d4++) {
                const int oq = 4 * (d4 ^ jq);
                const int ok = 4 * (d4 ^ jk);
                ulonglong2 Kp0 = *(const ulonglong2*)(Kb + ok);
                ulonglong2 Kp1 = *(const ulonglong2*)(Kb + DK + ok);
                #pragma unroll
                for (int i = 0; i < 4; i++) {
                    ulonglong2 Qp = *(const ulonglong2*)(Qb + i * DK + oq);
                    acc[i][0] = fma2(Qp.x, Kp0.x, acc[i][0]);
                    acc[i][1] = fma2(Qp.x, Kp1.x, acc[i][1]);
                    acc[i][0] = fma2(Qp.y, Kp0.y, acc[i][0]);
                    acc[i][1] = fma2(Qp.y, Kp1.y, acc[i][1]);
                }
            }
            #pragma unroll
            for (int i = 0; i < 4; i++) {
                sS[(q0 + i) * SSW + k0 + 2 * kh]     = lohi(acc[i][0]);
                sS[(q0 + i) * SSW + k0 + 2 * kh + 1] = lohi(acc[i][1]);
            }
        }
        __syncthreads();

        // ---- Row phase (special warp): exp*mask, sum, normalize, attn, W pairs ----
        if (wid == special && lane < SEQ) {
            const int q = lane;
            const float4* srow = (const float4*)(sS + q * SSW);
            const float4* mrow = (const float4*)(buf + OM + q * SEQ);
            float w[SEQ];
            float sum = 0.f;
            #pragma unroll
            for (int k4 = 0; k4 < SEQ / 4; k4++) {
                float4 sv = srow[k4];
                float4 mv = mrow[k4];
                w[k4 * 4 + 0] = __expf(sv.x * 0.125f) * mv.x;
                w[k4 * 4 + 1] = __expf(sv.y * 0.125f) * mv.y;
                w[k4 * 4 + 2] = __expf(sv.z * 0.125f) * mv.z;
                w[k4 * 4 + 3] = __expf(sv.w * 0.125f) * mv.w;
                sum += w[k4 * 4 + 0] + w[k4 * 4 + 1] + w[k4 * 4 + 2] + w[k4 * 4 + 3];
            }
            const float inv = 1.0f / (sum + 1e-8f);
            float4* Arow = (float4*)(attnOut + bh * (long)(SEQ * SEQ) + q * SEQ);
            #pragma unroll
            for (int k4 = 0; k4 < SEQ / 4; k4++) {
                float a0 = w[k4 * 4 + 0] * inv;
                float a1 = w[k4 * 4 + 1] * inv;
                float a2 = w[k4 * 4 + 2] * inv;
                float a3 = w[k4 * 4 + 3] * inv;
                Arow[k4] = make_float4(a0, a1, a2, a3);
                float w0 = a0 - fabsf((float)(q - (k4 * 4 + 0)));
                float w1 = a1 - fabsf((float)(q - (k4 * 4 + 1)));
                float w2 = a2 - fabsf((float)(q - (k4 * 4 + 2)));
                float w3 = a3 - fabsf((float)(q - (k4 * 4 + 3)));
                sW2[(k4 * 4 + 0) * WTS + q] = pack2(w0, w0);
                sW2[(k4 * 4 + 1) * WTS + q] = pack2(w1, w1);
                sW2[(k4 * 4 + 2) * WTS + q] = pack2(w2, w2);
                sW2[(k4 * 4 + 3) * WTS + q] = pack2(w3, w3);
            }
        }
        __syncthreads();

        // ---- Phase C: deAtt = W @ V, 4q x 4d tiles, f32x2, 3 non-special warps ----
        if (wid != special) {
            const int r  = (wid - special - 1) & 3;     // 0..2
            const int vt = r * 32 + lane;
            if (vt < 80) {
                const int d0 = 4 * (vt & 15);
                const int q0 = 4 * (vt >> 4);
                const int jd = d0 >> 2;
                const float* Vb = buf + OV;
                ull acc[4][2] = {};
                #pragma unroll
                for (int k = 0; k < SEQ; k++) {
                    ulonglong2 v  = *(const ulonglong2*)(Vb + k * DK + 4 * (jd ^ (k >> 2)));
                    ulonglong2 wA = *(const ulonglong2*)(sW2 + k * WTS + q0);
                    ulonglong2 wB = *(const ulonglong2*)(sW2 + k * WTS + q0 + 2);
                    acc[0][0] = fma2(wA.x, v.x, acc[0][0]);
                    acc[0][1] = fma2(wA.x, v.y, acc[0][1]);
                    acc[1][0] = fma2(wA.y, v.x, acc[1][0]);
                    acc[1][1] = fma2(wA.y, v.y, acc[1][1]);
                    acc[2][0] = fma2(wB.x, v.x, acc[2][0]);
                    acc[2][1] = fma2(wB.x, v.y, acc[2][1]);
                    acc[3][0] = fma2(wB.y, v.x, acc[3][0]);
                    acc[3][1] = fma2(wB.y, v.y, acc[3][1]);
                }
                const long base = bh * (long)(SEQ * DK);
                #pragma unroll
                for (int i = 0; i < 4; i++) {
                    float2 lo = unpack2(acc[i][0]);
                    float2 hi = unpack2(acc[i][1]);
                    *((float4*)(deAtt + base + (q0 + i) * DK + d0)) =
                        make_float4(lo.x, lo.y, hi.x, hi.y);
                }
            }
        }
        __syncthreads();   // sS/sW2/buf reuse fence
    }
}

extern "C" void kernel_launch(void* const* d_in, const int* in_sizes, int n_in,
                              void* d_out, int out_size)
{
    const float* Q = (const float*)d_in[0];
    const float* K = (const float*)d_in[1];
    const float* V = (const float*)d_in[2];
    const float* M = (const float*)d_in[3];

    const int total = in_sizes[0] / (SEQ * DK);          // 8192

    float* deAtt   = (float*)d_out;                      // [bh, SEQ, DK]
    float* attnOut = (float*)d_out + (long)in_sizes[0];  // [bh, SEQ, SEQ]

    const int grid = (total < GRID) ? total : GRID;
    sdpa_rel_kernel<<<grid, THREADS>>>(Q, K, V, M, deAtt, attnOut, total);
}

// round 16
// speedup vs baseline: 1.1067x; 1.1067x over previous
#include <cuda_runtime.h>
#include <cstdint>

#define SEQ 20
#define DK  64
#define THREADS 128
#define GRID 740              // persistent: 5 blocks/SM * 148 SMs

#define SSW 20                // sS row stride
#define TR 28                 // sWt row stride (float4-aligned)

// per-buffer float offsets (Q,K,V rows are 64 floats, XOR-swizzled slots)
#define OQ 0
#define OK 1280
#define OV 2560
#define OM 3840               // mask: 400 floats [q*20+k]
#define BUFB 4240             // floats per buffer (16960B)

typedef unsigned long long ull;

__device__ __forceinline__ ull fma2(ull a, ull b, ull c) {
    ull d;
    asm("fma.rn.f32x2 %0, %1, %2, %3;" : "=l"(d) : "l"(a), "l"(b), "l"(c));
    return d;
}
__device__ __forceinline__ float lohi(ull v) {
    float2 r;
    asm("mov.b64 {%0, %1}, %2;" : "=f"(r.x), "=f"(r.y) : "l"(v));
    return r.x + r.y;
}

__device__ __forceinline__ void cp16(unsigned int saddr, const void* g) {
    asm volatile("cp.async.cg.shared.global [%0], [%1], 16;" :: "r"(saddr), "l"(g));
}

// XOR swizzle: float4-slot c4 of row stored at slot (c4 ^ (row>>2)) & 15
__device__ __forceinline__ void issue_loads(const float4* __restrict__ Q4,
                                            const float4* __restrict__ K4,
                                            const float4* __restrict__ V4,
                                            const float4* __restrict__ M4,
                                            long bh, float* buf, int tid)
{
    unsigned int sb = (unsigned int)__cvta_generic_to_shared(buf);
    const float4* q = Q4 + bh * 320;
    const float4* k = K4 + bh * 320;
    const float4* v = V4 + bh * 320;
    #pragma unroll
    for (int r = 0; r < 3; r++) {
        int i = tid + r * THREADS;
        if (i < 320) {
            int row = i >> 4, c4 = i & 15;
            unsigned int off = (unsigned int)(row * DK + 4 * ((c4 ^ (row >> 2)) & 15)) * 4u;
            cp16(sb + (OQ * 4u) + off, q + i);
            cp16(sb + (OK * 4u) + off, k + i);
            cp16(sb + (OV * 4u) + off, v + i);
        }
    }
    if (tid < 100)
        cp16(sb + (OM + 4 * tid) * 4u, M4 + bh * 100 + tid);
}

__global__ __launch_bounds__(THREADS, 5)
void sdpa_rel_kernel(const float* __restrict__ Qg,
                     const float* __restrict__ Kg,
                     const float* __restrict__ Vg,
                     const float* __restrict__ Mg,
                     float* __restrict__ deAtt,
                     float* __restrict__ attnOut,
                     int total)
{
    __shared__ __align__(16) float sBuf[2 * BUFB];
    __shared__ __align__(16) float sS[SEQ * SSW];    // raw scores, row-major
    __shared__ __align__(16) float sWt[SEQ * TR];    // W transposed [k][q]

    const int tid  = threadIdx.x;
    const int wid  = tid >> 5;
    const int lane = tid & 31;
    const int G    = gridDim.x;

    const float4* Q4 = (const float4*)Qg;
    const float4* K4 = (const float4*)Kg;
    const float4* V4 = (const float4*)Vg;
    const float4* M4 = (const float4*)Mg;

    issue_loads(Q4, K4, V4, M4, blockIdx.x, sBuf, tid);
    asm volatile("cp.async.commit_group;" ::: "memory");

    int it = 0;
    for (long bh = blockIdx.x; bh < total; bh += G, it++) {
        float* buf = sBuf + (it & 1) * BUFB;

        if (bh + G < total) {
            issue_loads(Q4, K4, V4, M4, bh + G, sBuf + ((it + 1) & 1) * BUFB, tid);
            asm volatile("cp.async.commit_group;" ::: "memory");
            asm volatile("cp.async.wait_group 1;" ::: "memory");
        } else {
            asm volatile("cp.async.wait_group 0;" ::: "memory");
        }
        __syncthreads();

        const int special = (3 - it) & 3;        // warp doing A-half0 + row this iter
        const int helper  = special ^ 1;         // warp doing A-half1 (other SMSP)

        // ---- Phase A: S = Q K^T, 4q x (2+2)k tiles, 25 lanes on TWO warps ----
        if ((wid == special || wid == helper) && lane < 25) {
            const int kh = (wid == helper) ? 1 : 0;   // which pair of k-columns
            const int q0 = (lane / 5) * 4;
            const int k0 = (lane % 5) * 4;
            const int jq = q0 >> 2;
            const int jk = k0 >> 2;
            const float* Qb = buf + OQ + q0 * DK;
            const float* Kb = buf + OK + (k0 + 2 * kh) * DK;
            ull acc[4][2] = {};
            #pragma unroll
            for (int d4 = 0; d4 < DK / 4; d4++) {
                const int oq = 4 * (d4 ^ jq);
                const int ok = 4 * (d4 ^ jk);
                ulonglong2 Kp0 = *(const ulonglong2*)(Kb + ok);
                ulonglong2 Kp1 = *(const ulonglong2*)(Kb + DK + ok);
                #pragma unroll
                for (int i = 0; i < 4; i++) {
                    ulonglong2 Qp = *(const ulonglong2*)(Qb + i * DK + oq);
                    acc[i][0] = fma2(Qp.x, Kp0.x, acc[i][0]);
                    acc[i][1] = fma2(Qp.x, Kp1.x, acc[i][1]);
                    acc[i][0] = fma2(Qp.y, Kp0.y, acc[i][0]);
                    acc[i][1] = fma2(Qp.y, Kp1.y, acc[i][1]);
                }
            }
            #pragma unroll
            for (int i = 0; i < 4; i++) {
                sS[(q0 + i) * SSW + k0 + 2 * kh]     = lohi(acc[i][0]);
                sS[(q0 + i) * SSW + k0 + 2 * kh + 1] = lohi(acc[i][1]);
            }
        }
        __syncthreads();

        // ---- Row phase (special warp): exp*mask, sum, normalize, attn, W^T ----
        if (wid == special && lane < SEQ) {
            const int q = lane;
            const float4* srow = (const float4*)(sS + q * SSW);
            const float4* mrow = (const float4*)(buf + OM + q * SEQ);
            float w[SEQ];
            float sum = 0.f;
            #pragma unroll
            for (int k4 = 0; k4 < SEQ / 4; k4++) {
                float4 sv = srow[k4];
                float4 mv = mrow[k4];
                w[k4 * 4 + 0] = __expf(sv.x * 0.125f) * mv.x;
                w[k4 * 4 + 1] = __expf(sv.y * 0.125f) * mv.y;
                w[k4 * 4 + 2] = __expf(sv.z * 0.125f) * mv.z;
                w[k4 * 4 + 3] = __expf(sv.w * 0.125f) * mv.w;
                sum += w[k4 * 4 + 0] + w[k4 * 4 + 1] + w[k4 * 4 + 2] + w[k4 * 4 + 3];
            }
            const float inv = 1.0f / (sum + 1e-8f);
            float4* Arow = (float4*)(attnOut + bh * (long)(SEQ * SEQ) + q * SEQ);
            #pragma unroll
            for (int k4 = 0; k4 < SEQ / 4; k4++) {
                float a0 = w[k4 * 4 + 0] * inv;
                float a1 = w[k4 * 4 + 1] * inv;
                float a2 = w[k4 * 4 + 2] * inv;
                float a3 = w[k4 * 4 + 3] * inv;
                Arow[k4] = make_float4(a0, a1, a2, a3);
                sWt[(k4 * 4 + 0) * TR + q] = a0 - fabsf((float)(q - (k4 * 4 + 0)));
                sWt[(k4 * 4 + 1) * TR + q] = a1 - fabsf((float)(q - (k4 * 4 + 1)));
                sWt[(k4 * 4 + 2) * TR + q] = a2 - fabsf((float)(q - (k4 * 4 + 2)));
                sWt[(k4 * 4 + 3) * TR + q] = a3 - fabsf((float)(q - (k4 * 4 + 3)));
            }
        }
        __syncthreads();

        // ---- Phase C: deAtt = W @ V, 4q x 4d tiles, 80 lanes on 3 non-special warps ----
        if (wid != special) {
            const int r  = (wid - special - 1) & 3;     // 0..2
            const int vt = r * 32 + lane;
            if (vt < 80) {
                const int d0 = 4 * (vt & 15);
                const int q0 = 4 * (vt >> 4);
                const int jd = d0 >> 2;
                const float* Vb = buf + OV;
                const float* Wb = sWt + q0;
                float4 acc[4];
                #pragma unroll
                for (int i = 0; i < 4; i++) acc[i] = make_float4(0.f, 0.f, 0.f, 0.f);
                #pragma unroll
                for (int k = 0; k < SEQ; k++) {
                    float4 v = *(const float4*)(Vb + k * DK + 4 * (jd ^ (k >> 2)));
                    float4 w = *(const float4*)(Wb + k * TR);
                    acc[0].x = fmaf(w.x, v.x, acc[0].x);
                    acc[0].y = fmaf(w.x, v.y, acc[0].y);
                    acc[0].z = fmaf(w.x, v.z, acc[0].z);
                    acc[0].w = fmaf(w.x, v.w, acc[0].w);
                    acc[1].x = fmaf(w.y, v.x, acc[1].x);
                    acc[1].y = fmaf(w.y, v.y, acc[1].y);
                    acc[1].z = fmaf(w.y, v.z, acc[1].z);
                    acc[1].w = fmaf(w.y, v.w, acc[1].w);
                    acc[2].x = fmaf(w.z, v.x, acc[2].x);
                    acc[2].y = fmaf(w.z, v.y, acc[2].y);
                    acc[2].z = fmaf(w.z, v.z, acc[2].z);
                    acc[2].w = fmaf(w.z, v.w, acc[2].w);
                    acc[3].x = fmaf(w.w, v.x, acc[3].x);
                    acc[3].y = fmaf(w.w, v.y, acc[3].y);
                    acc[3].z = fmaf(w.w, v.z, acc[3].z);
                    acc[3].w = fmaf(w.w, v.w, acc[3].w);
                }
                const long base = bh * (long)(SEQ * DK);
                #pragma unroll
                for (int i = 0; i < 4; i++)
                    *((float4*)(deAtt + base + (q0 + i) * DK + d0)) = acc[i];
            }
        }
        __syncthreads();   // sS/sWt/buf reuse fence
    }
}

extern "C" void kernel_launch(void* const* d_in, const int* in_sizes, int n_in,
                              void* d_out, int out_size)
{
    const float* Q = (const float*)d_in[0];
    const float* K = (const float*)d_in[1];
    const float* V = (const float*)d_in[2];
    const float* M = (const float*)d_in[3];

    const int total = in_sizes[0] / (SEQ * DK);          // 8192

    float* deAtt   = (float*)d_out;                      // [bh, SEQ, DK]
    float* attnOut = (float*)d_out + (long)in_sizes[0];  // [bh, SEQ, SEQ]

    const int grid = (total < GRID) ? total : GRID;
    sdpa_rel_kernel<<<grid, THREADS>>>(Q, K, V, M, deAtt, attnOut, total);
}